// round 16
// baseline (speedup 1.0000x reference)
#include <cuda_runtime.h>
#include <cuda_fp16.h>
#include <cstdint>

#define CC     256
#define HWSZ   4096
#define KTOT   512       // x (256) then g (256)
#define PIXT   128       // pixels per CTA
#define KCH    128       // K per smem chunk
#define NCHUNK 4
#define NTHR   512
#define LN_EPS 1e-5f

// ---- W fp16 scratch (L2-resident, 256KB) ----
__device__ __half g_W_h[CC * KTOT];           // [o][k], k = ch (x) then 256+ch (g)

__device__ __forceinline__ uint32_t smem_u32(const void* p) {
    uint32_t a;
    asm("{ .reg .u64 t; cvta.to.shared.u64 t, %1; cvt.u32.u64 %0, t; }"
        : "=r"(a) : "l"(p));
    return a;
}

__device__ __forceinline__ void ldsm_x4(uint32_t* r, uint32_t a) {
    asm volatile("ldmatrix.sync.aligned.m8n8.x4.shared.b16 {%0,%1,%2,%3}, [%4];"
                 : "=r"(r[0]), "=r"(r[1]), "=r"(r[2]), "=r"(r[3]) : "r"(a));
}
__device__ __forceinline__ void ldsm_x4_t(uint32_t* r, uint32_t a) {
    asm volatile("ldmatrix.sync.aligned.m8n8.x4.trans.shared.b16 {%0,%1,%2,%3}, [%4];"
                 : "=r"(r[0]), "=r"(r[1]), "=r"(r[2]), "=r"(r[3]) : "r"(a));
}
__device__ __forceinline__ void mma_f16(float* c, const uint32_t* a,
                                        uint32_t b0, uint32_t b1) {
    asm volatile(
        "mma.sync.aligned.m16n8k16.row.col.f32.f16.f16.f32 "
        "{%0,%1,%2,%3}, {%4,%5,%6,%7}, {%8,%9}, {%0,%1,%2,%3};"
        : "+f"(c[0]), "+f"(c[1]), "+f"(c[2]), "+f"(c[3])
        : "r"(a[0]), "r"(a[1]), "r"(a[2]), "r"(a[3]), "r"(b0), "r"(b1));
}

#define CP_ASYNC16(sa, ga) \
    asm volatile("cp.async.cg.shared.global [%0], [%1], 16;" \
                 :: "r"(sa), "l"(ga) : "memory")
#define CP_COMMIT() asm volatile("cp.async.commit_group;" ::: "memory")
#define CP_WAIT0()  asm volatile("cp.async.wait_group 0;" ::: "memory")

__device__ __forceinline__ uint32_t pack_h2(float x0, float x1) {
    __half2 h = __floats2half2_rn(x0, x1);
    return *reinterpret_cast<uint32_t*>(&h);
}

// ---- prep: W -> fp16, layout [o][k0..511] ----
__global__ void prep_w(const float* __restrict__ Wx, const float* __restrict__ Wg)
{
    int idx = blockIdx.x * blockDim.x + threadIdx.x;   // 0..131071
    int o = idx >> 9, k = idx & 511;
    float v = (k < 256) ? Wx[o * 256 + k] : Wg[o * 256 + (k - 256)];
    g_W_h[idx] = __float2half(v);
}

// ---------------- smem layout (dynamic) ----------------
// A buffers: 2 slots of 128 rows x 272B ; B buffers: 2 slots of 256 rows x 272B
#define OFF_U     0
#define OFF_BXG   1024
#define OFF_SIG   2048      // 128 * 4B
#define OFF_SUMS  2560      // 128 px * 4 quarters * float4 = 8192
#define OFF_RED   10752     // 16 * float2
#define OFF_TOT   10880
#define A_REG     11264
#define A_STRIDE  272       // 128 px * 2B + 16 pad (ldsm conflict-free)
#define A_BUFSZ   34816     // 128 rows * 272
#define B_REG     (A_REG + 2 * A_BUFSZ)      // 80896
#define B_STRIDE  272       // 128 k * 2B + 16 pad (conflict-free)
#define B_BUFSZ   69632     // 256 rows * 272
#define SMEM_TOTAL (B_REG + 2 * B_BUFSZ)     // 220160 (~215KB, 1 CTA/SM)

__global__ void __launch_bounds__(NTHR, 1)
attn_gate_hmma(const float* __restrict__ x,
               const float* __restrict__ g,
               const float* __restrict__ ln_gamma,
               const float* __restrict__ ln_beta,
               const float* __restrict__ bxg,
               const float* __restrict__ Wpsi,
               const float* __restrict__ bpsi,
               float* __restrict__ out)
{
    extern __shared__ char smem[];
    const uint32_t sb = smem_u32(smem);
    const int tid = threadIdx.x;
    const int wid = tid >> 5, lid = tid & 31;
    const int pixgrp = wid >> 2;          // 0..3 (32 pixels each)
    const int nq     = wid & 3;           // 0..3 (64 channels each)
    const int b    = blockIdx.x >> 5;     // 32 pixel tiles per batch
    const int pix0 = (blockIdx.x & 31) * PIXT;

    float* sU   = (float*)(smem + OFF_U);
    float* sBxg = (float*)(smem + OFF_BXG);
    float* sSig = (float*)(smem + OFF_SIG);
    float4* sSums = (float4*)(smem + OFF_SUMS);
    float2* sRed  = (float2*)(smem + OFF_RED);
    float2* sTot  = (float2*)(smem + OFF_TOT);

    // ---- B tile: 256 rows x 256B; 512 threads = half-row (128B) each ----
    const int brow = tid >> 1;
    const int bseg = tid & 1;
    const uint32_t bdst_off = B_REG + brow * B_STRIDE + bseg * 128;

    #define CPA_B(c, buf) do {                                                 \
        uint32_t dst = sb + (buf) * B_BUFSZ + bdst_off;                        \
        const char* w = (const char*)(g_W_h + (size_t)brow * KTOT + (c) * KCH) \
                        + bseg * 128;                                          \
        CP_ASYNC16(dst,       w);       CP_ASYNC16(dst + 16,  w + 16);         \
        CP_ASYNC16(dst + 32,  w + 32);  CP_ASYNC16(dst + 48,  w + 48);         \
        CP_ASYNC16(dst + 64,  w + 64);  CP_ASYNC16(dst + 80,  w + 80);         \
        CP_ASYNC16(dst + 96,  w + 96);  CP_ASYNC16(dst + 112, w + 112);        \
    } while (0)

    // ---- A half-tile: 64 k-rows x 128 px; thread = 16 px of one row ----
    float4 pa[4];
    const int arow = tid >> 3;            // 0..63
    const int aseg = tid & 7;             // 16-px segment

    // chunk c: c<2 -> x channels (c*128..), c>=2 -> g channels ((c-2)*128..)
    #define LDG_A(c, half) do {                                                \
        const float* asrc = (((c) < 2) ? x : g) +                              \
            ((size_t)b * CC + ((c) & 1) * KCH + (half) * 64) * HWSZ + pix0 +   \
            (size_t)arow * HWSZ + aseg * 16;                                   \
        pa[0] = *(const float4*)(asrc);                                        \
        pa[1] = *(const float4*)(asrc + 4);                                    \
        pa[2] = *(const float4*)(asrc + 8);                                    \
        pa[3] = *(const float4*)(asrc + 12);                                   \
    } while (0)

    #define STS_A(abuf, half) do {                                             \
        char* base = smem + A_REG + (abuf) * A_BUFSZ +                         \
                     ((half) * 64 + arow) * A_STRIDE + aseg * 32;              \
        *(uint2*)(base)      = make_uint2(pack_h2(pa[0].x, pa[0].y),           \
                                          pack_h2(pa[0].z, pa[0].w));          \
        *(uint2*)(base + 8)  = make_uint2(pack_h2(pa[1].x, pa[1].y),           \
                                          pack_h2(pa[1].z, pa[1].w));          \
        *(uint2*)(base + 16) = make_uint2(pack_h2(pa[2].x, pa[2].y),           \
                                          pack_h2(pa[2].z, pa[2].w));          \
        *(uint2*)(base + 24) = make_uint2(pack_h2(pa[3].x, pa[3].y),           \
                                          pack_h2(pa[3].z, pa[3].w));          \
    } while (0)

    if (tid < 256) {   // epilogue params + totals (su = Σwpsi*gamma, ws = Σwpsi*beta)
        float wp = Wpsi[tid];
        float u  = wp * ln_gamma[tid];
        float wb = wp * ln_beta[tid];
        sU[tid]   = u;
        sBxg[tid] = bxg[tid];
        float us = u, ws = wb;
        #pragma unroll
        for (int m = 16; m >= 1; m >>= 1) {
            us += __shfl_xor_sync(0xffffffffu, us, m);
            ws += __shfl_xor_sync(0xffffffffu, ws, m);
        }
        if (lid == 0) sRed[wid] = make_float2(us, ws);
    }
    __syncthreads();
    if (tid == 0) {
        float us = 0.f, ws = 0.f;
        #pragma unroll
        for (int w = 0; w < 8; ++w) { us += sRed[w].x; ws += sRed[w].y; }
        sTot[0] = make_float2(us, ws);
    }

    float acc[2][8][4];                    // [mrow][n-col pair][quad]
    #pragma unroll
    for (int mr = 0; mr < 2; ++mr)
        #pragma unroll
        for (int j = 0; j < 8; ++j)
            #pragma unroll
            for (int q = 0; q < 4; ++q) acc[mr][j][q] = 0.f;

    // prologue: B chunk 0 in flight; A chunk 0 staged (both halves)
    CPA_B(0, 0);
    CP_COMMIT();
    LDG_A(0, 0);
    STS_A(0, 0);
    LDG_A(0, 1);
    STS_A(0, 1);
    CP_WAIT0();
    __syncthreads();

    const int m0 = pixgrp * 32;
    const int al_k = (lid & 7) + ((lid >> 4) << 3);
    const int al_m = m0 + (((lid >> 3) & 1) << 3);
    const int bl_n = ((lid >> 4) << 3) + (lid & 7);
    const int bl_k = ((lid >> 3) & 1) << 3;

    for (int c = 0; c < NCHUNK; ++c) {
        if (c < NCHUNK - 1) {
            CPA_B(c + 1, (c + 1) & 1);
            CP_COMMIT();
            LDG_A(c + 1, 0);
        }

        const uint32_t ta = sb + A_REG + (c & 1) * A_BUFSZ;
        const uint32_t b_base = sb + B_REG + (c & 1) * B_BUFSZ +
                                (nq * 64 + bl_n) * B_STRIDE + bl_k * 2;

        #pragma unroll
        for (int ks = 0; ks < 4; ++ks) {
            const uint32_t a_addr = ta + (ks * 16 + al_k) * A_STRIDE + al_m * 2;
            uint32_t a0[4], a1[4];
            ldsm_x4_t(a0, a_addr);
            ldsm_x4_t(a1, a_addr + 32);            // m + 16 px
            #pragma unroll
            for (int ntt = 0; ntt < 4; ++ntt) {
                const uint32_t ba = b_base + ntt * 16 * B_STRIDE + ks * 32;
                uint32_t bh[4];
                ldsm_x4(bh, ba);
                const int j = ntt * 2;
                mma_f16(acc[0][j],     a0, bh[0], bh[1]);
                mma_f16(acc[1][j],     a1, bh[0], bh[1]);
                mma_f16(acc[0][j + 1], a0, bh[2], bh[3]);
                mma_f16(acc[1][j + 1], a1, bh[2], bh[3]);
            }
        }

        if (c < NCHUNK - 1) {
            STS_A((c + 1) & 1, 0);      // half0 staged; fetch half1
            LDG_A(c + 1, 1);
        }

        #pragma unroll
        for (int ks = 4; ks < 8; ++ks) {
            const uint32_t a_addr = ta + (ks * 16 + al_k) * A_STRIDE + al_m * 2;
            uint32_t a0[4], a1[4];
            ldsm_x4_t(a0, a_addr);
            ldsm_x4_t(a1, a_addr + 32);
            #pragma unroll
            for (int ntt = 0; ntt < 4; ++ntt) {
                const uint32_t ba = b_base + ntt * 16 * B_STRIDE + ks * 32;
                uint32_t bh[4];
                ldsm_x4(bh, ba);
                const int j = ntt * 2;
                mma_f16(acc[0][j],     a0, bh[0], bh[1]);
                mma_f16(acc[1][j],     a1, bh[0], bh[1]);
                mma_f16(acc[0][j + 1], a0, bh[2], bh[3]);
                mma_f16(acc[1][j + 1], a1, bh[2], bh[3]);
            }
        }

        if (c < NCHUNK - 1) {
            STS_A((c + 1) & 1, 1);
            CP_WAIT0();                 // B(c+1) landed (one group in flight)
        }
        __syncthreads();
    }

    // ---- epilogue: relu(+bias), LN over 256 ch, psi, sigmoid ----
    // rows: pixgrp*32 + mr*16 + (lid>>2) and +8 ; cols nq*64 + j*8 + 2*(lid&3)+{0,1}
    {
        float s1[2][2], s2[2][2], sy[2][2];
        #pragma unroll
        for (int mr = 0; mr < 2; ++mr)
            #pragma unroll
            for (int h = 0; h < 2; ++h) { s1[mr][h] = 0.f; s2[mr][h] = 0.f; sy[mr][h] = 0.f; }

        #pragma unroll
        for (int mr = 0; mr < 2; ++mr) {
            #pragma unroll
            for (int j = 0; j < 8; ++j) {
                const int c0 = nq * 64 + j * 8 + 2 * (lid & 3);
                const float bx0 = sBxg[c0], bx1 = sBxg[c0 + 1];
                const float u0 = sU[c0], u1 = sU[c0 + 1];
                float y;
                y = fmaxf(acc[mr][j][0] + bx0, 0.f); s1[mr][0] += y; s2[mr][0] += y * y; sy[mr][0] += u0 * y;
                y = fmaxf(acc[mr][j][1] + bx1, 0.f); s1[mr][0] += y; s2[mr][0] += y * y; sy[mr][0] += u1 * y;
                y = fmaxf(acc[mr][j][2] + bx0, 0.f); s1[mr][1] += y; s2[mr][1] += y * y; sy[mr][1] += u0 * y;
                y = fmaxf(acc[mr][j][3] + bx1, 0.f); s1[mr][1] += y; s2[mr][1] += y * y; sy[mr][1] += u1 * y;
            }
        }
        #pragma unroll
        for (int m = 1; m <= 2; m <<= 1) {
            #pragma unroll
            for (int mr = 0; mr < 2; ++mr)
                #pragma unroll
                for (int h = 0; h < 2; ++h) {
                    s1[mr][h] += __shfl_xor_sync(0xffffffffu, s1[mr][h], m);
                    s2[mr][h] += __shfl_xor_sync(0xffffffffu, s2[mr][h], m);
                    sy[mr][h] += __shfl_xor_sync(0xffffffffu, sy[mr][h], m);
                }
        }
        if ((lid & 3) == 0) {
            #pragma unroll
            for (int mr = 0; mr < 2; ++mr) {
                const int p = pixgrp * 32 + mr * 16 + (lid >> 2);
                sSums[p * 4 + nq]       = make_float4(s1[mr][0], s2[mr][0], sy[mr][0], 0.f);
                sSums[(p + 8) * 4 + nq] = make_float4(s1[mr][1], s2[mr][1], sy[mr][1], 0.f);
            }
        }
    }
    __syncthreads();
    if (tid < PIXT) {
        float4 h0 = sSums[tid * 4], h1 = sSums[tid * 4 + 1];
        float4 h2 = sSums[tid * 4 + 2], h3 = sSums[tid * 4 + 3];
        float s1 = h0.x + h1.x + h2.x + h3.x;
        float s2 = h0.y + h1.y + h2.y + h3.y;
        float sy = h0.z + h1.z + h2.z + h3.z;
        float2 tot = sTot[0];
        float mean = s1 * (1.f / 256.f);
        float var  = s2 * (1.f / 256.f) - mean * mean;
        float rstd = rsqrtf(var + LN_EPS);
        float z = rstd * (sy - mean * tot.x) + tot.y + bpsi[0];
        sSig[tid] = 1.f / (1.f + expf(-z));
    }
    __syncthreads();

    // ---- gate: out[b,o,pix] = sig[pix] * x[b,o,pix] ----
    const size_t xbase = (size_t)b * CC * HWSZ + pix0;
    const int pq = tid & 31;              // 32 pixel-quads = 128 px
    float4 sg = *(const float4*)(sSig + pq * 4);
    #pragma unroll
    for (int it = 0; it < 16; ++it) {
        const int o = (tid >> 5) + it * 16;
        const size_t off = xbase + (size_t)o * HWSZ + pq * 4;
        float4 xv = *(const float4*)(x + off);
        float4 ov;
        ov.x = sg.x * xv.x; ov.y = sg.y * xv.y;
        ov.z = sg.z * xv.z; ov.w = sg.w * xv.w;
        *(float4*)(out + off) = ov;
    }
}

extern "C" void kernel_launch(void* const* d_in, const int* in_sizes, int n_in,
                              void* d_out, int out_size)
{
    const float* x        = (const float*)d_in[0];
    const float* g        = (const float*)d_in[1];
    const float* Wx       = (const float*)d_in[2];
    const float* Wg       = (const float*)d_in[3];
    const float* Wpsi     = (const float*)d_in[4];
    const float* ln_gamma = (const float*)d_in[5];
    const float* ln_beta  = (const float*)d_in[6];
    const float* bxg      = (const float*)d_in[7];
    const float* bpsi     = (const float*)d_in[8];
    float* out = (float*)d_out;

    cudaFuncSetAttribute(attn_gate_hmma,
                         cudaFuncAttributeMaxDynamicSharedMemorySize, SMEM_TOTAL);

    prep_w<<<512, 256>>>(Wx, Wg);
    attn_gate_hmma<<<512, NTHR, SMEM_TOTAL>>>(x, g, ln_gamma, ln_beta, bxg,
                                              Wpsi, bpsi, out);
}

// round 17
// speedup vs baseline: 1.7078x; 1.7078x over previous
#include <cuda_runtime.h>
#include <cuda_fp16.h>
#include <cstdint>

#define CC     256
#define HWSZ   4096
#define KTOT   512       // x (256) then g (256)
#define PIXT   128       // pixels per CTA
#define KCH    64        // K per smem chunk
#define NCHUNK 8
#define NTHR   512
#define LN_EPS 1e-5f

// ---- W fp16 scratch (L2-resident, 256KB) ----
__device__ __half g_W_h[CC * KTOT];           // [o][k], k = ch (x) then 256+ch (g)

__device__ __forceinline__ uint32_t smem_u32(const void* p) {
    uint32_t a;
    asm("{ .reg .u64 t; cvta.to.shared.u64 t, %1; cvt.u32.u64 %0, t; }"
        : "=r"(a) : "l"(p));
    return a;
}

__device__ __forceinline__ void ldsm_x4(uint32_t* r, uint32_t a) {
    asm volatile("ldmatrix.sync.aligned.m8n8.x4.shared.b16 {%0,%1,%2,%3}, [%4];"
                 : "=r"(r[0]), "=r"(r[1]), "=r"(r[2]), "=r"(r[3]) : "r"(a));
}
__device__ __forceinline__ void ldsm_x4_t(uint32_t* r, uint32_t a) {
    asm volatile("ldmatrix.sync.aligned.m8n8.x4.trans.shared.b16 {%0,%1,%2,%3}, [%4];"
                 : "=r"(r[0]), "=r"(r[1]), "=r"(r[2]), "=r"(r[3]) : "r"(a));
}
__device__ __forceinline__ void mma_f16(float* c, const uint32_t* a,
                                        uint32_t b0, uint32_t b1) {
    asm volatile(
        "mma.sync.aligned.m16n8k16.row.col.f32.f16.f16.f32 "
        "{%0,%1,%2,%3}, {%4,%5,%6,%7}, {%8,%9}, {%0,%1,%2,%3};"
        : "+f"(c[0]), "+f"(c[1]), "+f"(c[2]), "+f"(c[3])
        : "r"(a[0]), "r"(a[1]), "r"(a[2]), "r"(a[3]), "r"(b0), "r"(b1));
}

#define CP_ASYNC16(sa, ga) \
    asm volatile("cp.async.cg.shared.global [%0], [%1], 16;" \
                 :: "r"(sa), "l"(ga) : "memory")
#define CP_COMMIT() asm volatile("cp.async.commit_group;" ::: "memory")
#define CP_WAIT0()  asm volatile("cp.async.wait_group 0;" ::: "memory")

__device__ __forceinline__ uint32_t pack_h2(float x0, float x1) {
    __half2 h = __floats2half2_rn(x0, x1);
    return *reinterpret_cast<uint32_t*>(&h);
}

// ---- prep: W -> fp16, layout [o][k0..511] ----
__global__ void prep_w(const float* __restrict__ Wx, const float* __restrict__ Wg)
{
    int idx = blockIdx.x * blockDim.x + threadIdx.x;   // 0..131071
    int o = idx >> 9, k = idx & 511;
    float v = (k < 256) ? Wx[o * 256 + k] : Wg[o * 256 + (k - 256)];
    g_W_h[idx] = __float2half(v);
}

// ---------------- smem layout (dynamic) ----------------
// A buffers: 6 slots of 64 rows x 272B (x-chunks 0-3 persistent, g-chunks use 4/5)
// B buffers: 2 slots of 256 rows x 144B
#define OFF_U     0
#define OFF_BXG   1024
#define OFF_SIG   2048      // 128 * 4B
#define OFF_SUMS  2560      // 128 px * 4 quarters * float4 = 8192
#define OFF_RED   10752     // 16 * float2
#define OFF_TOT   10880
#define A_REG     11264
#define A_STRIDE  272       // 128 px * 2B + 16 pad (ldsm conflict-free)
#define A_BUFSZ   17408     // 64 rows * 272
#define B_REG     (A_REG + 6 * A_BUFSZ)      // 115712
#define B_STRIDE  144       // 64 k * 2B + 16 pad
#define B_BUFSZ   36864     // 256 rows * 144
#define SMEM_TOTAL (B_REG + 2 * B_BUFSZ)     // 189440  (1 CTA/SM)

__global__ void __launch_bounds__(NTHR, 1)
attn_gate_hmma(const float* __restrict__ x,
               const float* __restrict__ g,
               const float* __restrict__ ln_gamma,
               const float* __restrict__ ln_beta,
               const float* __restrict__ bxg,
               const float* __restrict__ Wpsi,
               const float* __restrict__ bpsi,
               float* __restrict__ out)
{
    extern __shared__ char smem[];
    const uint32_t sb = smem_u32(smem);
    const int tid = threadIdx.x;
    const int wid = tid >> 5, lid = tid & 31;
    const int pixgrp = wid >> 2;          // 0..3 (32 pixels each)
    const int nq     = wid & 3;           // 0..3 (64 channels each)
    const int b    = blockIdx.x >> 5;     // 32 pixel tiles per batch
    const int pix0 = (blockIdx.x & 31) * PIXT;

    float* sU   = (float*)(smem + OFF_U);
    float* sBxg = (float*)(smem + OFF_BXG);
    float* sSig = (float*)(smem + OFF_SIG);
    float4* sSums = (float4*)(smem + OFF_SUMS);
    float2* sRed  = (float2*)(smem + OFF_RED);
    float2* sTot  = (float2*)(smem + OFF_TOT);

    // A buffer index per chunk: x chunks persist in 0..3; g chunks ping-pong 4/5
    #define ABUF(c) (((c) < 4) ? (c) : (4 + ((c) & 1)))

    // ---- B tile: 256 rows x 128B; 512 threads = half-row (64B) each ----
    const int brow = tid >> 1;
    const int bseg = tid & 1;
    const uint32_t bdst_off = B_REG + brow * B_STRIDE + bseg * 64;

    #define CPA_B(c, buf) do {                                                 \
        uint32_t dst = sb + (buf) * B_BUFSZ + bdst_off;                        \
        const char* w = (const char*)(g_W_h + (size_t)brow * KTOT + (c) * KCH) \
                        + bseg * 64;                                           \
        CP_ASYNC16(dst,      w);      CP_ASYNC16(dst + 16, w + 16);            \
        CP_ASYNC16(dst + 32, w + 32); CP_ASYNC16(dst + 48, w + 48);            \
    } while (0)

    // ---- A tile: 64 k-rows x 128 px; thread = 16 px of one row ----
    float4 pa[4];
    const int arow = tid >> 3;            // 0..63
    const int aseg = tid & 7;             // 16-px segment

    #define LDG_A(c) do {                                                      \
        const float* asrc = (((c) < 4) ? x : g) +                              \
            ((size_t)b * CC + ((c) & 3) * KCH) * HWSZ + pix0 +                 \
            (size_t)arow * HWSZ + aseg * 16;                                   \
        pa[0] = *(const float4*)(asrc);                                        \
        pa[1] = *(const float4*)(asrc + 4);                                    \
        pa[2] = *(const float4*)(asrc + 8);                                    \
        pa[3] = *(const float4*)(asrc + 12);                                   \
    } while (0)

    #define STS_A(abuf) do {                                                   \
        char* base = smem + A_REG + (abuf) * A_BUFSZ +                         \
                     arow * A_STRIDE + aseg * 32;                              \
        *(uint2*)(base)      = make_uint2(pack_h2(pa[0].x, pa[0].y),           \
                                          pack_h2(pa[0].z, pa[0].w));          \
        *(uint2*)(base + 8)  = make_uint2(pack_h2(pa[1].x, pa[1].y),           \
                                          pack_h2(pa[1].z, pa[1].w));          \
        *(uint2*)(base + 16) = make_uint2(pack_h2(pa[2].x, pa[2].y),           \
                                          pack_h2(pa[2].z, pa[2].w));          \
        *(uint2*)(base + 24) = make_uint2(pack_h2(pa[3].x, pa[3].y),           \
                                          pack_h2(pa[3].z, pa[3].w));          \
    } while (0)

    if (tid < 256) {   // epilogue params + totals (su = Σwpsi*gamma, ws = Σwpsi*beta)
        float wp = Wpsi[tid];
        float u  = wp * ln_gamma[tid];
        float wb = wp * ln_beta[tid];
        sU[tid]   = u;
        sBxg[tid] = bxg[tid];
        float us = u, ws = wb;
        #pragma unroll
        for (int m = 16; m >= 1; m >>= 1) {
            us += __shfl_xor_sync(0xffffffffu, us, m);
            ws += __shfl_xor_sync(0xffffffffu, ws, m);
        }
        if (lid == 0) sRed[wid] = make_float2(us, ws);
    }
    __syncthreads();
    if (tid == 0) {
        float us = 0.f, ws = 0.f;
        #pragma unroll
        for (int w = 0; w < 8; ++w) { us += sRed[w].x; ws += sRed[w].y; }
        sTot[0] = make_float2(us, ws);
    }

    float acc[2][8][4];                    // [mrow][n-col pair][quad]
    #pragma unroll
    for (int mr = 0; mr < 2; ++mr)
        #pragma unroll
        for (int j = 0; j < 8; ++j)
            #pragma unroll
            for (int q = 0; q < 4; ++q) acc[mr][j][q] = 0.f;

    // prologue: chunk 0 into buffers 0
    CPA_B(0, 0);
    CP_COMMIT();
    LDG_A(0);
    STS_A(0);
    CP_WAIT0();
    __syncthreads();

    const int m0 = pixgrp * 32;
    const int al_k = (lid & 7) + ((lid >> 4) << 3);
    const int al_m = m0 + (((lid >> 3) & 1) << 3);
    const int bl_n = ((lid >> 4) << 3) + (lid & 7);
    const int bl_k = ((lid >> 3) & 1) << 3;

    // one k-step (16 k) of the warp tile: 2 A-ldsm + 4 x (B-ldsm + 4 MMA)
    #define MMA_KSTEP(ks) do {                                                 \
        const uint32_t a_addr = ta + ((ks) * 16 + al_k) * A_STRIDE + al_m * 2; \
        uint32_t a0[4], a1[4];                                                 \
        ldsm_x4_t(a0, a_addr);                                                 \
        ldsm_x4_t(a1, a_addr + 32);            /* m + 16 px */                 \
        _Pragma("unroll")                                                      \
        for (int ntt = 0; ntt < 4; ++ntt) {                                    \
            const uint32_t ba = b_base + ntt * 16 * B_STRIDE + (ks) * 32;      \
            uint32_t bh[4];                                                    \
            ldsm_x4(bh, ba);                                                   \
            const int j = ntt * 2;                                             \
            mma_f16(acc[0][j],     a0, bh[0], bh[1]);                          \
            mma_f16(acc[1][j],     a1, bh[0], bh[1]);                          \
            mma_f16(acc[0][j + 1], a0, bh[2], bh[3]);                          \
            mma_f16(acc[1][j + 1], a1, bh[2], bh[3]);                          \
        }                                                                      \
    } while (0)

    for (int c = 0; c < NCHUNK; ++c) {
        if (c < NCHUNK - 1) {
            CPA_B(c + 1, (c + 1) & 1);
            CP_COMMIT();
            LDG_A(c + 1);
        }

        const uint32_t ta = sb + A_REG + ABUF(c) * A_BUFSZ;
        const uint32_t b_base = sb + (c & 1) * B_BUFSZ + B_REG +
                                (nq * 64 + bl_n) * B_STRIDE + bl_k * 2;

        // first half of the MMA work (ks = 0,1) while LDG_A(c+1) flies
        MMA_KSTEP(0);
        MMA_KSTEP(1);

        // mid-chunk: stage A(c+1) into smem, retire pa regs, start B drain
        if (c < NCHUNK - 1) {
            STS_A(ABUF(c + 1));
            CP_WAIT0();
        }

        // second half (ks = 2,3) overlaps the STS/cp.async completion window
        MMA_KSTEP(2);
        MMA_KSTEP(3);

        __syncthreads();
    }

    // ---- epilogue: relu(+bias), LN over 256 ch, psi, sigmoid ----
    // rows: pixgrp*32 + mr*16 + (lid>>2) and +8 ; cols nq*64 + j*8 + 2*(lid&3)+{0,1}
    {
        float s1[2][2], s2[2][2], sy[2][2];
        #pragma unroll
        for (int mr = 0; mr < 2; ++mr)
            #pragma unroll
            for (int h = 0; h < 2; ++h) { s1[mr][h] = 0.f; s2[mr][h] = 0.f; sy[mr][h] = 0.f; }

        #pragma unroll
        for (int mr = 0; mr < 2; ++mr) {
            #pragma unroll
            for (int j = 0; j < 8; ++j) {
                const int c0 = nq * 64 + j * 8 + 2 * (lid & 3);
                const float bx0 = sBxg[c0], bx1 = sBxg[c0 + 1];
                const float u0 = sU[c0], u1 = sU[c0 + 1];
                float y;
                y = fmaxf(acc[mr][j][0] + bx0, 0.f); s1[mr][0] += y; s2[mr][0] += y * y; sy[mr][0] += u0 * y;
                y = fmaxf(acc[mr][j][1] + bx1, 0.f); s1[mr][0] += y; s2[mr][0] += y * y; sy[mr][0] += u1 * y;
                y = fmaxf(acc[mr][j][2] + bx0, 0.f); s1[mr][1] += y; s2[mr][1] += y * y; sy[mr][1] += u0 * y;
                y = fmaxf(acc[mr][j][3] + bx1, 0.f); s1[mr][1] += y; s2[mr][1] += y * y; sy[mr][1] += u1 * y;
            }
        }
        #pragma unroll
        for (int m = 1; m <= 2; m <<= 1) {
            #pragma unroll
            for (int mr = 0; mr < 2; ++mr)
                #pragma unroll
                for (int h = 0; h < 2; ++h) {
                    s1[mr][h] += __shfl_xor_sync(0xffffffffu, s1[mr][h], m);
                    s2[mr][h] += __shfl_xor_sync(0xffffffffu, s2[mr][h], m);
                    sy[mr][h] += __shfl_xor_sync(0xffffffffu, sy[mr][h], m);
                }
        }
        if ((lid & 3) == 0) {
            #pragma unroll
            for (int mr = 0; mr < 2; ++mr) {
                const int p = pixgrp * 32 + mr * 16 + (lid >> 2);
                sSums[p * 4 + nq]       = make_float4(s1[mr][0], s2[mr][0], sy[mr][0], 0.f);
                sSums[(p + 8) * 4 + nq] = make_float4(s1[mr][1], s2[mr][1], sy[mr][1], 0.f);
            }
        }
    }
    __syncthreads();
    if (tid < PIXT) {
        float4 h0 = sSums[tid * 4], h1 = sSums[tid * 4 + 1];
        float4 h2 = sSums[tid * 4 + 2], h3 = sSums[tid * 4 + 3];
        float s1 = h0.x + h1.x + h2.x + h3.x;
        float s2 = h0.y + h1.y + h2.y + h3.y;
        float sy = h0.z + h1.z + h2.z + h3.z;
        float2 tot = sTot[0];
        float mean = s1 * (1.f / 256.f);
        float var  = s2 * (1.f / 256.f) - mean * mean;
        float rstd = rsqrtf(var + LN_EPS);
        float z = rstd * (sy - mean * tot.x) + tot.y + bpsi[0];
        sSig[tid] = 1.f / (1.f + expf(-z));
    }
    __syncthreads();

    // ---- gate: out[b,o,pix] = sig[pix] * fp16x_smem[o][pix]  (no x re-read) ----
    const size_t obase = (size_t)b * CC * HWSZ + pix0;
    const int pq = tid & 31;              // 32 pixel-quads = 128 px
    float4 sg = *(const float4*)(sSig + pq * 4);
    #pragma unroll
    for (int it = 0; it < 16; ++it) {
        const int o = (tid >> 5) + it * 16;
        // x channel o lives in A buffer o>>6, row o&63 (stored fp16 during chunks 0-3)
        const char* asrc = smem + A_REG + (o >> 6) * A_BUFSZ + (o & 63) * A_STRIDE + pq * 8;
        uint2 hx = *(const uint2*)(asrc);
        float2 x01 = __half22float2(*reinterpret_cast<const __half2*>(&hx.x));
        float2 x23 = __half22float2(*reinterpret_cast<const __half2*>(&hx.y));
        float4 ov;
        ov.x = sg.x * x01.x; ov.y = sg.y * x01.y;
        ov.z = sg.z * x23.x; ov.w = sg.w * x23.y;
        *(float4*)(out + obase + (size_t)o * HWSZ + pq * 4) = ov;
    }
}

extern "C" void kernel_launch(void* const* d_in, const int* in_sizes, int n_in,
                              void* d_out, int out_size)
{
    const float* x        = (const float*)d_in[0];
    const float* g        = (const float*)d_in[1];
    const float* Wx       = (const float*)d_in[2];
    const float* Wg       = (const float*)d_in[3];
    const float* Wpsi     = (const float*)d_in[4];
    const float* ln_gamma = (const float*)d_in[5];
    const float* ln_beta  = (const float*)d_in[6];
    const float* bxg      = (const float*)d_in[7];
    const float* bpsi     = (const float*)d_in[8];
    float* out = (float*)d_out;

    cudaFuncSetAttribute(attn_gate_hmma,
                         cudaFuncAttributeMaxDynamicSharedMemorySize, SMEM_TOTAL);

    prep_w<<<512, 256>>>(Wx, Wg);
    attn_gate_hmma<<<512, NTHR, SMEM_TOTAL>>>(x, g, ln_gamma, ln_beta, bxg,
                                              Wpsi, bpsi, out);
}